// round 3
// baseline (speedup 1.0000x reference)
#include <cuda_runtime.h>
#include <cuda_bf16.h>

#define N_NODES 100000
#define N_EDGES 1600000
#define D 32
#define ED 8

// Ping-pong node features
__device__ float g_buf0[N_NODES * D];
__device__ float g_buf1[N_NODES * D];
// CSR build
__device__ int  g_count[N_NODES];
__device__ int  g_rowptr[N_NODES + 1];
__device__ int  g_cursor[N_NODES];
__device__ int2 g_sorted[N_EDGES];   // (src, eid) sorted by dst

// ---------------------------------------------------------------------------
// 1) zero in-degree counters
// ---------------------------------------------------------------------------
__global__ void zero_counts_kernel() {
    for (int i = blockIdx.x * blockDim.x + threadIdx.x; i < N_NODES;
         i += gridDim.x * blockDim.x)
        g_count[i] = 0;
}

// ---------------------------------------------------------------------------
// 2) histogram of dst (spread int atomics)
// ---------------------------------------------------------------------------
__global__ void hist_kernel(const int* __restrict__ dst) {
    for (int e = blockIdx.x * blockDim.x + threadIdx.x; e < N_EDGES;
         e += gridDim.x * blockDim.x)
        atomicAdd(&g_count[dst[e]], 1);
}

// ---------------------------------------------------------------------------
// 3) exclusive scan over counts -> row_ptr, and init cursors.
//    Single block, 1024 threads, warp-shuffle scan, chunked with carry.
// ---------------------------------------------------------------------------
__global__ __launch_bounds__(1024) void scan_kernel() {
    __shared__ int warp_tot[32];
    __shared__ int chunk_tot;
    const int tid  = threadIdx.x;
    const int lane = tid & 31;
    const int w    = tid >> 5;
    int carry = 0;

    for (int base = 0; base < N_NODES; base += 1024) {
        const int i = base + tid;
        int v = (i < N_NODES) ? g_count[i] : 0;

        // warp inclusive scan
        int incl = v;
#pragma unroll
        for (int off = 1; off < 32; off <<= 1) {
            int t = __shfl_up_sync(0xffffffffu, incl, off);
            if (lane >= off) incl += t;
        }
        if (lane == 31) warp_tot[w] = incl;
        __syncthreads();

        if (w == 0) {
            int t  = warp_tot[lane];
            int ti = t;
#pragma unroll
            for (int off = 1; off < 32; off <<= 1) {
                int u = __shfl_up_sync(0xffffffffu, ti, off);
                if (lane >= off) ti += u;
            }
            warp_tot[lane] = ti - t;            // exclusive warp offset
            if (lane == 31) chunk_tot = ti;     // total of this chunk
        }
        __syncthreads();

        const int excl = incl - v + warp_tot[w] + carry;
        if (i < N_NODES) {
            g_rowptr[i] = excl;
            g_cursor[i] = excl;
        }
        carry += chunk_tot;
        __syncthreads();   // warp_tot reused next iteration
    }
    if (tid == 0) g_rowptr[N_NODES] = carry;
}

// ---------------------------------------------------------------------------
// 4) scatter edges into CSR order: g_sorted[pos] = (src, eid)
// ---------------------------------------------------------------------------
__global__ void scatter_kernel(const int* __restrict__ src,
                               const int* __restrict__ dst) {
    for (int e = blockIdx.x * blockDim.x + threadIdx.x; e < N_EDGES;
         e += gridDim.x * blockDim.x) {
        const int d   = dst[e];
        const int pos = atomicAdd(&g_cursor[d], 1);
        g_sorted[pos] = make_int2(src[e], e);
    }
}

// ---------------------------------------------------------------------------
// Fused per-layer kernel: warp per node.
//   acc_j = sum_{edges} relu(x[src][j] + be[j] + sum_k ea[eid][k]*We[k][j])
//   h     = x[n] + acc
//   out   = leaky_relu(h @ W + b)
// No atomics, no agg buffer.
// ---------------------------------------------------------------------------
__global__ __launch_bounds__(256) void layer_kernel(
    const float* __restrict__ x_ext, int x_sel,
    float* __restrict__ out_ext, int out_sel,
    const float* __restrict__ edge_attr,
    const float* __restrict__ We,   // [8, 32]
    const float* __restrict__ be,   // [32]
    const float* __restrict__ W,    // [32, 32]
    const float* __restrict__ b)    // [32]
{
    const float* x  = (x_sel == 0) ? x_ext : (x_sel == 1 ? g_buf0 : g_buf1);
    float* out = (out_sel == 0) ? out_ext : (out_sel == 1 ? g_buf0 : g_buf1);

    const int lane = threadIdx.x & 31;
    const int wid  = (blockIdx.x * blockDim.x + threadIdx.x) >> 5;
    const int nw   = (gridDim.x * blockDim.x) >> 5;

    float we[ED];
#pragma unroll
    for (int k = 0; k < ED; k++) we[k] = We[k * D + lane];
    const float ebias = be[lane];

    float wn[D];
#pragma unroll
    for (int k = 0; k < D; k++) wn[k] = W[k * D + lane];
    const float nbias = b[lane];

    for (int node = wid; node < N_NODES; node += nw) {
        const int beg = __ldg(&g_rowptr[node]);
        const int end = __ldg(&g_rowptr[node + 1]);

        float acc = 0.0f;
        int j = beg;
        // unroll-2 software pipeline for MLP on the 2-level gather
        for (; j + 1 < end; j += 2) {
            const int2 se0 = g_sorted[j];
            const int2 se1 = g_sorted[j + 1];
            const float av0 = __ldg(edge_attr + se0.y * ED + (lane & 7));
            const float av1 = __ldg(edge_attr + se1.y * ED + (lane & 7));
            const float xv0 = __ldg(x + se0.x * D + lane);
            const float xv1 = __ldg(x + se1.x * D + lane);
            float e0 = ebias, e1 = ebias;
#pragma unroll
            for (int k = 0; k < ED; k++) {
                e0 = fmaf(__shfl_sync(0xffffffffu, av0, k), we[k], e0);
                e1 = fmaf(__shfl_sync(0xffffffffu, av1, k), we[k], e1);
            }
            acc += fmaxf(xv0 + e0, 0.0f);
            acc += fmaxf(xv1 + e1, 0.0f);
        }
        if (j < end) {
            const int2 se = g_sorted[j];
            const float av = __ldg(edge_attr + se.y * ED + (lane & 7));
            const float xv = __ldg(x + se.x * D + lane);
            float e = ebias;
#pragma unroll
            for (int k = 0; k < ED; k++)
                e = fmaf(__shfl_sync(0xffffffffu, av, k), we[k], e);
            acc += fmaxf(xv + e, 0.0f);
        }

        const float h = x[node * D + lane] + acc;
        float o = nbias;
#pragma unroll
        for (int k = 0; k < D; k++)
            o = fmaf(__shfl_sync(0xffffffffu, h, k), wn[k], o);
        out[node * D + lane] = fmaxf(o, 0.01f * o);  // leaky_relu 0.01
    }
}

// ---------------------------------------------------------------------------
extern "C" void kernel_launch(void* const* d_in, const int* in_sizes, int n_in,
                              void* d_out, int out_size)
{
    const float* x   = (const float*)d_in[0];
    const float* ea  = (const float*)d_in[1];
    const float* W   = (const float*)d_in[2];
    const float* b   = (const float*)d_in[3];
    const float* We  = (const float*)d_in[4];
    const float* be  = (const float*)d_in[5];
    const int*   ei  = (const int*)d_in[6];
    float* out = (float*)d_out;

    const int* src = ei;
    const int* dst = ei + N_EDGES;

    // CSR build (once per call)
    zero_counts_kernel<<<196, 512>>>();
    hist_kernel<<<1184, 256>>>(dst);
    scan_kernel<<<1, 1024>>>();
    scatter_kernel<<<1184, 256>>>(src, dst);

    // 3 fused layers; ping-pong ext -> g_buf0 -> g_buf1 -> d_out
    const int x_sels[3]   = {0, 1, 2};
    const int out_sels[3] = {1, 2, 0};
    for (int l = 0; l < 3; l++) {
        layer_kernel<<<1184, 256>>>(
            x, x_sels[l], out, out_sels[l],
            ea, We + l * ED * D, be + l * D, W + l * D * D, b + l * D);
    }
}

// round 4
// speedup vs baseline: 2.0395x; 2.0395x over previous
#include <cuda_runtime.h>
#include <cuda_bf16.h>

#define N_NODES 100000
#define N_EDGES 1600000
#define D 32
#define ED 8

// Ping-pong node features + aggregation buffer.
__device__ float g_buf0[N_NODES * D];
__device__ float g_buf1[N_NODES * D];
__device__ float g_agg[N_NODES * D];

// ---------------------------------------------------------------------------
// Zero the aggregation buffer (float4 grid-stride). ~6us measured.
// ---------------------------------------------------------------------------
__global__ void zero_agg_kernel() {
    const int n4 = N_NODES * D / 4;
    float4* p = reinterpret_cast<float4*>(g_agg);
    float4 z = make_float4(0.f, 0.f, 0.f, 0.f);
    for (int i = blockIdx.x * blockDim.x + threadIdx.x; i < n4;
         i += gridDim.x * blockDim.x) {
        p[i] = z;
    }
}

// ---------------------------------------------------------------------------
// Edge kernel: 8 edges per warp per iteration (2 independent 4-edge groups
// for MLP=2 on the x-row gathers and the RED.128 scatters).
//   lane layout: g = lane>>3 selects edge-in-quad, c = lane&7 selects a
//   column quad (columns 4c..4c+3).
// ---------------------------------------------------------------------------
__global__ __launch_bounds__(256) void edge_kernel(
    const float* __restrict__ x_ext, int x_sel,
    const float* __restrict__ edge_attr,
    const float* __restrict__ We,   // layer slice: [8, 32]
    const float* __restrict__ be,   // layer slice: [32]
    const int*   __restrict__ src,
    const int*   __restrict__ dst)
{
    const float* x = (x_sel == 0) ? x_ext : (x_sel == 1 ? g_buf0 : g_buf1);

    const int lane = threadIdx.x & 31;
    const int c    = lane & 7;    // column quad index
    const int g    = lane >> 3;   // edge within the 4-edge group
    const int wid  = (blockIdx.x * blockDim.x + threadIdx.x) >> 5;
    const int nw   = (gridDim.x * blockDim.x) >> 5;

    // We column quad for this lane: We[k][4c..4c+3], k = 0..7
    float4 wv[ED];
#pragma unroll
    for (int k = 0; k < ED; k++)
        wv[k] = *reinterpret_cast<const float4*>(We + k * D + c * 4);
    const float4 bias = *reinterpret_cast<const float4*>(be + c * 4);

    // N_EDGES % 8 == 0, so every iteration is a full 8-edge tile.
    for (int e8 = wid * 8; e8 < N_EDGES; e8 += nw * 8) {
        // Front-load all independent memory ops (idx, attrs, gathers).
        const int s0 = __ldg(src + e8 + g);
        const int d0 = __ldg(dst + e8 + g);
        const int s1 = __ldg(src + e8 + 4 + g);
        const int d1 = __ldg(dst + e8 + 4 + g);
        const float av0 = __ldg(edge_attr + e8 * ED + lane);        // edges e8..e8+3
        const float av1 = __ldg(edge_attr + (e8 + 4) * ED + lane);  // edges e8+4..e8+7
        const float4 xv0 =
            __ldg(reinterpret_cast<const float4*>(x + s0 * D + c * 4));
        const float4 xv1 =
            __ldg(reinterpret_cast<const float4*>(x + s1 * D + c * 4));

        float4 a0 = bias, a1 = bias;
#pragma unroll
        for (int k = 0; k < ED; k++) {
            const float f0 = __shfl_sync(0xffffffffu, av0, (g << 3) | k);
            const float f1 = __shfl_sync(0xffffffffu, av1, (g << 3) | k);
            a0.x = fmaf(f0, wv[k].x, a0.x);
            a0.y = fmaf(f0, wv[k].y, a0.y);
            a0.z = fmaf(f0, wv[k].z, a0.z);
            a0.w = fmaf(f0, wv[k].w, a0.w);
            a1.x = fmaf(f1, wv[k].x, a1.x);
            a1.y = fmaf(f1, wv[k].y, a1.y);
            a1.z = fmaf(f1, wv[k].z, a1.z);
            a1.w = fmaf(f1, wv[k].w, a1.w);
        }

        float4 m0, m1;
        m0.x = fmaxf(xv0.x + a0.x, 0.0f);
        m0.y = fmaxf(xv0.y + a0.y, 0.0f);
        m0.z = fmaxf(xv0.z + a0.z, 0.0f);
        m0.w = fmaxf(xv0.w + a0.w, 0.0f);
        m1.x = fmaxf(xv1.x + a1.x, 0.0f);
        m1.y = fmaxf(xv1.y + a1.y, 0.0f);
        m1.z = fmaxf(xv1.z + a1.z, 0.0f);
        m1.w = fmaxf(xv1.w + a1.w, 0.0f);

        float* p0 = g_agg + d0 * D + c * 4;
        float* p1 = g_agg + d1 * D + c * 4;
        asm volatile("red.global.add.v4.f32 [%0], {%1,%2,%3,%4};"
                     :: "l"(p0), "f"(m0.x), "f"(m0.y), "f"(m0.z), "f"(m0.w)
                     : "memory");
        asm volatile("red.global.add.v4.f32 [%0], {%1,%2,%3,%4};"
                     :: "l"(p1), "f"(m1.x), "f"(m1.y), "f"(m1.z), "f"(m1.w)
                     : "memory");
    }
}

// ---------------------------------------------------------------------------
// Node kernel (pure R1 form): one warp per node, lane = output column j.
//   h_k = x[node][k] + agg[node][k]
//   o_j = leaky_relu(b[j] + sum_k h_k * W[k][j])
// ---------------------------------------------------------------------------
__global__ __launch_bounds__(256) void node_kernel(
    const float* __restrict__ x_ext, int x_sel,
    float* __restrict__ out_ext, int out_sel,
    const float* __restrict__ W,    // layer slice: [32, 32]
    const float* __restrict__ b)    // layer slice: [32]
{
    const float* x  = (x_sel == 0) ? x_ext : (x_sel == 1 ? g_buf0 : g_buf1);
    float* out = (out_sel == 0) ? out_ext : (out_sel == 1 ? g_buf0 : g_buf1);

    const int lane = threadIdx.x & 31;
    const int wid  = (blockIdx.x * blockDim.x + threadIdx.x) >> 5;
    const int nw   = (gridDim.x * blockDim.x) >> 5;

    float w[D];
#pragma unroll
    for (int k = 0; k < D; k++) w[k] = W[k * D + lane];
    const float bias = b[lane];

    for (int node = wid; node < N_NODES; node += nw) {
        const float h = x[node * D + lane] + g_agg[node * D + lane];
        float acc = bias;
#pragma unroll
        for (int k = 0; k < D; k++)
            acc = fmaf(__shfl_sync(0xffffffffu, h, k), w[k], acc);
        out[node * D + lane] = fmaxf(acc, 0.01f * acc);  // leaky_relu 0.01
    }
}

// ---------------------------------------------------------------------------
// 3 layers of { zero agg; edge scatter; node transform }.
// Ping-pong: ext -> g_buf0 -> g_buf1 -> d_out.
// ---------------------------------------------------------------------------
extern "C" void kernel_launch(void* const* d_in, const int* in_sizes, int n_in,
                              void* d_out, int out_size)
{
    const float* x   = (const float*)d_in[0];   // [N, 32]
    const float* ea  = (const float*)d_in[1];   // [E, 8]
    const float* W   = (const float*)d_in[2];   // [3, 32, 32]
    const float* b   = (const float*)d_in[3];   // [3, 32]
    const float* We  = (const float*)d_in[4];   // [3, 8, 32]
    const float* be  = (const float*)d_in[5];   // [3, 32]
    const int*   ei  = (const int*)d_in[6];     // [2, E] int32
    float* out = (float*)d_out;

    const int* src = ei;
    const int* dst = ei + N_EDGES;

    const int x_sels[3]   = {0, 1, 2};
    const int out_sels[3] = {1, 2, 0};

    for (int l = 0; l < 3; l++) {
        zero_agg_kernel<<<1184, 256>>>();
        edge_kernel<<<1184, 256>>>(
            x, x_sels[l], ea, We + l * ED * D, be + l * D, src, dst);
        node_kernel<<<592, 256>>>(
            x, x_sels[l], out, out_sels[l], W + l * D * D, b + l * D);
    }
}